// round 15
// baseline (speedup 1.0000x reference)
#include <cuda_runtime.h>
#include <cstdint>

// Pin accurate log regardless of harness fast-math flags.
extern "C" __device__ float __nv_logf(float);

// ---------------------------------------------------------------------------
// JAX threefry2x32, exact: rotations {13,15,26,6,17,29,16,24}, 5+1 injections
// ---------------------------------------------------------------------------
#define TFRND(r) { x0 += x1; x1 = __funnelshift_l(x1, x1, (r)); x1 ^= x0; }

__device__ __forceinline__ uint2 threefry2x32(uint32_t k0, uint32_t k1,
                                              uint32_t x0, uint32_t x1) {
    uint32_t k2 = k0 ^ k1 ^ 0x1BD11BDAu;
    x0 += k0; x1 += k1;
    TFRND(13) TFRND(15) TFRND(26) TFRND(6)
    x0 += k1; x1 += k2 + 1u;
    TFRND(17) TFRND(29) TFRND(16) TFRND(24)
    x0 += k2; x1 += k0 + 2u;
    TFRND(13) TFRND(15) TFRND(26) TFRND(6)
    x0 += k0; x1 += k1 + 3u;
    TFRND(17) TFRND(29) TFRND(16) TFRND(24)
    x0 += k1; x1 += k2 + 4u;
    TFRND(13) TFRND(15) TFRND(26) TFRND(6)
    x0 += k2; x1 += k0 + 5u;
    return make_uint2(x0, x1);
}

// 32-bit random bits, partitionable mode: one block per element, xor halves.
__device__ __forceinline__ uint32_t tf_bits32(uint32_t k0, uint32_t k1, uint32_t idx) {
    uint2 r = threefry2x32(k0, k1, 0u, idx);
    return r.x ^ r.y;
}

// ---------------------------------------------------------------------------
// XLA ErfInv f32 (Giles poly) with XLA Log1p: u=a+1; d=u-1;
// log1p = (d==0) ? a : log(u)*a/d.  Branchy form (rare arms) = fewest instrs.
// ---------------------------------------------------------------------------
__device__ __forceinline__ float erfinv_xla(float x) {
    float a = __fmul_rn(-x, x);
    float u = __fadd_rn(a, 1.0f);
    float d = __fadd_rn(u, -1.0f);
    float l;
    if (d == 0.0f) {
        l = a;
    } else {
        l = __fdiv_rn(__fmul_rn(__nv_logf(u), a), d);
    }
    float w = -l;
    float p;
    if (w < 5.0f) {
        w = __fadd_rn(w, -2.5f);
        p = 2.81022636e-08f;
        p = fmaf(p, w, 3.43273939e-07f);
        p = fmaf(p, w, -3.5233877e-06f);
        p = fmaf(p, w, -4.39150654e-06f);
        p = fmaf(p, w, 0.00021858087f);
        p = fmaf(p, w, -0.00125372503f);
        p = fmaf(p, w, -0.00417768164f);
        p = fmaf(p, w, 0.246640727f);
        p = fmaf(p, w, 1.50140941f);
    } else {
        w = __fadd_rn(__fsqrt_rn(w), -3.0f);
        p = -0.000200214257f;
        p = fmaf(p, w, 0.000100950558f);
        p = fmaf(p, w, 0.00134934322f);
        p = fmaf(p, w, -0.00367342844f);
        p = fmaf(p, w, 0.00573950773f);
        p = fmaf(p, w, -0.0076224613f);
        p = fmaf(p, w, 0.00943887047f);
        p = fmaf(p, w, 1.00167406f);
        p = fmaf(p, w, 2.83297682f);
    }
    return __fmul_rn(p, x);
}

// State-independent noise: bits -> N(0,1)*0.1, exact XLA sequence.
__device__ __forceinline__ float noise_from_bits(uint32_t nb) {
    const float LO = -0.99999994039535522461f;     // nextafterf(-1, 0)
    const float SQRT2 = 1.41421353816986083984f;   // f32(np.sqrt(2))
    float fn = __fadd_rn(__uint_as_float((nb >> 9) | 0x3f800000u), -1.0f);
    float un = fmaxf(LO, __fadd_rn(__fmul_rn(fn, 2.0f), LO));
    float nrm = __fmul_rn(SQRT2, erfinv_xla(un));
    return __fmul_rn(nrm, 0.1f);
}

// ---------------------------------------------------------------------------
// XLA fast-tanh f32 (Eigen rational poly), logistic = 0.5 + 0.5*tanh(x/2)
// ---------------------------------------------------------------------------
__device__ __forceinline__ float tanh_xla(float x) {
    const float kClamp = 7.90531110763549805f;
    float cx = fminf(fmaxf(x, -kClamp), kClamp);
    float x2 = __fmul_rn(cx, cx);
    float np_;
    np_ = fmaf(x2, -2.76076847742355e-16f, 2.00018790482477e-13f);
    np_ = fmaf(x2, np_, -8.60467152213735e-11f);
    np_ = fmaf(x2, np_, 5.12229709037114e-08f);
    np_ = fmaf(x2, np_, 1.48572235717979e-05f);
    np_ = fmaf(x2, np_, 6.37261928875436e-04f);
    np_ = fmaf(x2, np_, 4.89352455891786e-03f);
    float num = __fmul_rn(cx, np_);
    float dq;
    dq = fmaf(x2, 1.19825839466702e-06f, 1.18534705686654e-04f);
    dq = fmaf(x2, dq, 2.26843463243900e-03f);
    dq = fmaf(x2, dq, 4.89352518554385e-03f);
    float r = __fdiv_rn(num, dq);
    return (fabsf(x) < 0.0004f) ? x : r;
}

__device__ __forceinline__ float sigmoid_xla(float x) {
    return fmaf(0.5f, tanh_xla(__fmul_rn(0.5f, x)), 0.5f);
}

// ---------------------------------------------------------------------------
// Per-step (noise_key, spike_key), partitionable semantics:
//   key_t = tf((0,42),(0,t));  k_noise = tf(key_t,(0,0));  k_spike = tf(key_t,(0,1))
// ---------------------------------------------------------------------------
__device__ uint4 g_stepkeys[512];

__global__ void lif_init_keys(int T) {
    int t = blockIdx.x * blockDim.x + threadIdx.x;
    if (t >= T) return;
    uint2 kt = threefry2x32(0u, 42u, 0u, (uint32_t)t);
    uint2 kn = threefry2x32(kt.x, kt.y, 0u, 0u);
    uint2 ks = threefry2x32(kt.x, kt.y, 0u, 1u);
    g_stepkeys[t] = make_uint4(kn.x, kn.y, ks.x, ks.y);
}

// ---------------------------------------------------------------------------
// State-dependent part of one neuron-step (noise precomputed), bit-identical
// float sequence to the XLA lowering.
// ---------------------------------------------------------------------------
__device__ __forceinline__ void lif_update(
    float& V, float& Th, float& ad, float& sy, float nm,
    float Iin, float noise, uint32_t ub,
    float& sf_out, float& v_out)
{
    // I_eff = I*syn + neuromod - adapt   (unfused)
    float Ieff = __fadd_rn(__fadd_rn(__fmul_rn(Iin, sy), nm), -ad);
    // V = V + (I_eff - V)*0.05 + noise   (unfused)
    float dV = __fmul_rn(__fadd_rn(Ieff, -V), 0.05f);
    V = __fadd_rn(__fadd_rn(V, dV), noise);

    // spike: uniform(0,1) < sigmoid(V - Vth)
    float p  = sigmoid_xla(__fadd_rn(V, -Th));
    float uu = __fadd_rn(__uint_as_float((ub >> 9) | 0x3f800000u), -1.0f);
    bool spk = uu < p;

    V = spk ? 0.0f : V;

    float Th_ns = __fadd_rn(Th, -__fmul_rn(0.1f, __fadd_rn(Th, -1.0f)));
    Th = spk ? __fadd_rn(Th, 0.1f) : Th_ns;
    Th = fminf(fmaxf(Th, 0.5f), 2.0f);

    float sf = spk ? 1.0f : 0.0f;
    ad = __fadd_rn(__fmul_rn(ad, 0.9f), __fmul_rn(0.5f, sf));
    float t1 = __fadd_rn(1.0f, -__fmul_rn(0.1f, sf));
    float t2 = __fmul_rn(0.05f, __fadd_rn(1.0f, -sy));
    sy = __fadd_rn(__fmul_rn(sy, t1), t2);

    sf_out = sf;
    v_out = V;
}

// ---------------------------------------------------------------------------
// Main kernel: exact R11 structure (2 neurons/thread, branch-free threefry
// filler for step t+1 ahead of step t's branchy float phase, running
// pointers), with the T-loop unrolled x2 so the pipeline's rotation copies
// (nba=nba_n; ...) are renamed away and loop-control overhead halves.
// Block = 32: 4096 blocks, ~27/SM, near-perfect balance.
// ---------------------------------------------------------------------------
__global__ void __launch_bounds__(32, 28)
lif_main(const float* __restrict__ I,
         const float* __restrict__ V0,  const float* __restrict__ Vth0,
         const float* __restrict__ ad0, const float* __restrict__ sy0,
         const float* __restrict__ nm0,
         float* __restrict__ out, int T, int BN)
{
    const int tid = blockIdx.x * blockDim.x + threadIdx.x;
    const int n0 = tid * 2;
    if (n0 >= BN) return;

    float2 Vv  = ((const float2*)V0)[tid];
    float2 Thv = ((const float2*)Vth0)[tid];
    float2 adv = ((const float2*)ad0)[tid];
    float2 syv = ((const float2*)sy0)[tid];
    const float2 nmv = ((const float2*)nm0)[tid];

    float Va = Vv.x,  Vb = Vv.y;
    float Ta = Thv.x, Tb = Thv.y;
    float aa = adv.x, ab = adv.y;
    float sa = syv.x, sb = syv.y;

    // Running pointers: advance by BN floats per step (no per-iter IMAD).
    const float* __restrict__ ip = I + (size_t)n0;
    float* __restrict__ sp = out + (size_t)n0;
    float* __restrict__ vp = out + (size_t)T * (size_t)BN + (size_t)n0;

    // Prologue: bits for step 0.
    uint4 k = g_stepkeys[0];
    uint32_t nba = tf_bits32(k.x, k.y, (uint32_t)n0);
    uint32_t nbb = tf_bits32(k.x, k.y, (uint32_t)(n0 + 1));
    uint32_t uba = tf_bits32(k.z, k.w, (uint32_t)n0);
    uint32_t ubb = tf_bits32(k.z, k.w, (uint32_t)(n0 + 1));

    #pragma unroll 2
    for (int t = 0; t < T; ++t) {
        // --- branch-free filler: step t+1's threefry (288 independent ALU
        //     ops) scheduled into the float chains below ---
        const int tn = (t + 1 < T) ? (t + 1) : t;
        const uint4 kn = g_stepkeys[tn];
        const uint32_t nba_n = tf_bits32(kn.x, kn.y, (uint32_t)n0);
        const uint32_t nbb_n = tf_bits32(kn.x, kn.y, (uint32_t)(n0 + 1));
        const uint32_t uba_n = tf_bits32(kn.z, kn.w, (uint32_t)n0);
        const uint32_t ubb_n = tf_bits32(kn.z, kn.w, (uint32_t)(n0 + 1));

        const float2 Iv = *(const float2*)ip;

        // --- step t float phase (consumes bits from last iteration) ---
        float noia = noise_from_bits(nba);
        float noib = noise_from_bits(nbb);

        float spa, va, spb, vb;
        lif_update(Va, Ta, aa, sa, nmv.x, Iv.x, noia, uba, spa, va);
        lif_update(Vb, Tb, ab, sb, nmv.y, Iv.y, noib, ubb, spb, vb);

        *(float2*)sp = make_float2(spa, spb);
        *(float2*)vp = make_float2(va, vb);

        ip += BN; sp += BN; vp += BN;
        nba = nba_n; nbb = nbb_n; uba = uba_n; ubb = ubb_n;
    }
}

// ---------------------------------------------------------------------------
// Launch. Graph-capturable: kernel launches only.
// ---------------------------------------------------------------------------
extern "C" void kernel_launch(void* const* d_in, const int* in_sizes, int n_in,
                              void* d_out, int out_size) {
    const float* input = (const float*)d_in[0];
    const float* V0    = (const float*)d_in[1];
    const float* Vth0  = (const float*)d_in[2];
    const float* ad0   = (const float*)d_in[3];
    const float* sy0   = (const float*)d_in[4];
    const float* nm0   = (const float*)d_in[5];

    const int BN = in_sizes[1];              // B*N
    const int T  = in_sizes[0] / BN;         // time steps

    lif_init_keys<<<(T + 127) / 128, 128>>>(T);

    const int threads = 32;                  // 1-warp blocks: 4096 blocks
    const int nthreads_total = BN / 2;
    const int blocks = (nthreads_total + threads - 1) / threads;
    lif_main<<<blocks, threads>>>(input, V0, Vth0, ad0, sy0, nm0,
                                  (float*)d_out, T, BN);
}

// round 16
// speedup vs baseline: 1.0576x; 1.0576x over previous
#include <cuda_runtime.h>
#include <cstdint>

// Pin accurate log regardless of harness fast-math flags.
extern "C" __device__ float __nv_logf(float);

// ---------------------------------------------------------------------------
// JAX threefry2x32, exact: rotations {13,15,26,6,17,29,16,24}, 5+1 injections
// ---------------------------------------------------------------------------
#define TFRND(r) { x0 += x1; x1 = __funnelshift_l(x1, x1, (r)); x1 ^= x0; }

__device__ __forceinline__ uint2 threefry2x32(uint32_t k0, uint32_t k1,
                                              uint32_t x0, uint32_t x1) {
    uint32_t k2 = k0 ^ k1 ^ 0x1BD11BDAu;
    x0 += k0; x1 += k1;
    TFRND(13) TFRND(15) TFRND(26) TFRND(6)
    x0 += k1; x1 += k2 + 1u;
    TFRND(17) TFRND(29) TFRND(16) TFRND(24)
    x0 += k2; x1 += k0 + 2u;
    TFRND(13) TFRND(15) TFRND(26) TFRND(6)
    x0 += k0; x1 += k1 + 3u;
    TFRND(17) TFRND(29) TFRND(16) TFRND(24)
    x0 += k1; x1 += k2 + 4u;
    TFRND(13) TFRND(15) TFRND(26) TFRND(6)
    x0 += k2; x1 += k0 + 5u;
    return make_uint2(x0, x1);
}

// 32-bit random bits, partitionable mode: one block per element, xor halves.
__device__ __forceinline__ uint32_t tf_bits32(uint32_t k0, uint32_t k1, uint32_t idx) {
    uint2 r = threefry2x32(k0, k1, 0u, idx);
    return r.x ^ r.y;
}

// ---------------------------------------------------------------------------
// XLA ErfInv f32 (Giles poly) with XLA Log1p: u=a+1; d=u-1;
// log1p = (d==0) ? a : log(u)*a/d.  Branchy form (rare arms) = fewest instrs.
// ---------------------------------------------------------------------------
__device__ __forceinline__ float erfinv_xla(float x) {
    float a = __fmul_rn(-x, x);
    float u = __fadd_rn(a, 1.0f);
    float d = __fadd_rn(u, -1.0f);
    float l;
    if (d == 0.0f) {
        l = a;
    } else {
        l = __fdiv_rn(__fmul_rn(__nv_logf(u), a), d);
    }
    float w = -l;
    float p;
    if (w < 5.0f) {
        w = __fadd_rn(w, -2.5f);
        p = 2.81022636e-08f;
        p = fmaf(p, w, 3.43273939e-07f);
        p = fmaf(p, w, -3.5233877e-06f);
        p = fmaf(p, w, -4.39150654e-06f);
        p = fmaf(p, w, 0.00021858087f);
        p = fmaf(p, w, -0.00125372503f);
        p = fmaf(p, w, -0.00417768164f);
        p = fmaf(p, w, 0.246640727f);
        p = fmaf(p, w, 1.50140941f);
    } else {
        w = __fadd_rn(__fsqrt_rn(w), -3.0f);
        p = -0.000200214257f;
        p = fmaf(p, w, 0.000100950558f);
        p = fmaf(p, w, 0.00134934322f);
        p = fmaf(p, w, -0.00367342844f);
        p = fmaf(p, w, 0.00573950773f);
        p = fmaf(p, w, -0.0076224613f);
        p = fmaf(p, w, 0.00943887047f);
        p = fmaf(p, w, 1.00167406f);
        p = fmaf(p, w, 2.83297682f);
    }
    return __fmul_rn(p, x);
}

// ---------------------------------------------------------------------------
// XLA fast-tanh f32 (Eigen rational poly), logistic = 0.5 + 0.5*tanh(x/2)
// ---------------------------------------------------------------------------
__device__ __forceinline__ float tanh_xla(float x) {
    const float kClamp = 7.90531110763549805f;
    float cx = fminf(fmaxf(x, -kClamp), kClamp);
    float x2 = __fmul_rn(cx, cx);
    float np_;
    np_ = fmaf(x2, -2.76076847742355e-16f, 2.00018790482477e-13f);
    np_ = fmaf(x2, np_, -8.60467152213735e-11f);
    np_ = fmaf(x2, np_, 5.12229709037114e-08f);
    np_ = fmaf(x2, np_, 1.48572235717979e-05f);
    np_ = fmaf(x2, np_, 6.37261928875436e-04f);
    np_ = fmaf(x2, np_, 4.89352455891786e-03f);
    float num = __fmul_rn(cx, np_);
    float dq;
    dq = fmaf(x2, 1.19825839466702e-06f, 1.18534705686654e-04f);
    dq = fmaf(x2, dq, 2.26843463243900e-03f);
    dq = fmaf(x2, dq, 4.89352518554385e-03f);
    float r = __fdiv_rn(num, dq);
    return (fabsf(x) < 0.0004f) ? x : r;
}

__device__ __forceinline__ float sigmoid_xla(float x) {
    return fmaf(0.5f, tanh_xla(__fmul_rn(0.5f, x)), 0.5f);
}

// ---------------------------------------------------------------------------
// Per-step (noise_key, spike_key), partitionable semantics:
//   key_t = tf((0,42),(0,t));  k_noise = tf(key_t,(0,0));  k_spike = tf(key_t,(0,1))
// 512 entries, zero-initialized: reading index T (last-iter prefetch) is
// deterministic and its results are never consumed.
// ---------------------------------------------------------------------------
__device__ uint4 g_stepkeys[512];

__global__ void lif_init_keys(int T) {
    int t = blockIdx.x * blockDim.x + threadIdx.x;
    if (t >= T) return;
    uint2 kt = threefry2x32(0u, 42u, 0u, (uint32_t)t);
    uint2 kn = threefry2x32(kt.x, kt.y, 0u, 0u);
    uint2 ks = threefry2x32(kt.x, kt.y, 0u, 1u);
    g_stepkeys[t] = make_uint4(kn.x, kn.y, ks.x, ks.y);
}

// ---------------------------------------------------------------------------
// One neuron-step, bit-identical float sequence to the XLA lowering.
// ---------------------------------------------------------------------------
__device__ __forceinline__ void lif_update(
    float& V, float& Th, float& ad, float& sy, float nm,
    float Iin, uint32_t nb, uint32_t ub,
    float& sf_out, float& v_out)
{
    const float LO = -0.99999994039535522461f;     // nextafterf(-1, 0)
    const float SQRT2 = 1.41421353816986083984f;   // f32(np.sqrt(2))

    // noise = 0.1 * (sqrt2 * erfinv(uniform(LO, 1)))
    float fn = __fadd_rn(__uint_as_float((nb >> 9) | 0x3f800000u), -1.0f);
    float un = fmaxf(LO, __fadd_rn(__fmul_rn(fn, 2.0f), LO));
    float nrm = __fmul_rn(SQRT2, erfinv_xla(un));
    float noise = __fmul_rn(nrm, 0.1f);

    // I_eff = I*syn + neuromod - adapt   (unfused)
    float Ieff = __fadd_rn(__fadd_rn(__fmul_rn(Iin, sy), nm), -ad);
    // V = V + (I_eff - V)*0.05 + noise   (unfused)
    float dV = __fmul_rn(__fadd_rn(Ieff, -V), 0.05f);
    V = __fadd_rn(__fadd_rn(V, dV), noise);

    // spike: uniform(0,1) < sigmoid(V - Vth)
    float p  = sigmoid_xla(__fadd_rn(V, -Th));
    float uu = __fadd_rn(__uint_as_float((ub >> 9) | 0x3f800000u), -1.0f);
    bool spk = uu < p;

    V = spk ? 0.0f : V;

    float Th_ns = __fadd_rn(Th, -__fmul_rn(0.1f, __fadd_rn(Th, -1.0f)));
    Th = spk ? __fadd_rn(Th, 0.1f) : Th_ns;
    Th = fminf(fmaxf(Th, 0.5f), 2.0f);

    float sf = spk ? 1.0f : 0.0f;
    ad = __fadd_rn(__fmul_rn(ad, 0.9f), __fmul_rn(0.5f, sf));
    float t1 = __fadd_rn(1.0f, -__fmul_rn(0.1f, sf));
    float t2 = __fmul_rn(0.05f, __fadd_rn(1.0f, -sy));
    sy = __fadd_rn(__fmul_rn(sy, t1), t2);

    sf_out = sf;
    v_out = V;
}

// ---------------------------------------------------------------------------
// Main kernel (committed-best R11 structure, unroll 1): 2 adjacent neurons
// per thread; step t+1's threefry (288 straight-line ALU ops) computed
// before step t's branchy float phase so the scheduler fills the float
// chains' latency bubbles; running pointers; float2 I/O.
// Only change vs R11: unconditional g_stepkeys[t+1] prefetch (no select;
// index T reads the zero entry, results discarded).
// Block = 32: 4096 blocks, ~27/SM, near-perfect balance.
// ---------------------------------------------------------------------------
__global__ void __launch_bounds__(32, 28)
lif_main(const float* __restrict__ I,
         const float* __restrict__ V0,  const float* __restrict__ Vth0,
         const float* __restrict__ ad0, const float* __restrict__ sy0,
         const float* __restrict__ nm0,
         float* __restrict__ out, int T, int BN)
{
    const int tid = blockIdx.x * blockDim.x + threadIdx.x;
    const int n0 = tid * 2;
    if (n0 >= BN) return;

    float2 Vv  = ((const float2*)V0)[tid];
    float2 Thv = ((const float2*)Vth0)[tid];
    float2 adv = ((const float2*)ad0)[tid];
    float2 syv = ((const float2*)sy0)[tid];
    const float2 nmv = ((const float2*)nm0)[tid];

    float Va = Vv.x,  Vb = Vv.y;
    float Ta = Thv.x, Tb = Thv.y;
    float aa = adv.x, ab = adv.y;
    float sa = syv.x, sb = syv.y;

    // Running pointers: advance by BN floats per step (no per-iter IMAD).
    const float* __restrict__ ip = I + (size_t)n0;
    float* __restrict__ sp = out + (size_t)n0;
    float* __restrict__ vp = out + (size_t)T * (size_t)BN + (size_t)n0;

    // Prologue: bits for step 0.
    uint4 k = g_stepkeys[0];
    uint32_t nba = tf_bits32(k.x, k.y, (uint32_t)n0);
    uint32_t nbb = tf_bits32(k.x, k.y, (uint32_t)(n0 + 1));
    uint32_t uba = tf_bits32(k.z, k.w, (uint32_t)n0);
    uint32_t ubb = tf_bits32(k.z, k.w, (uint32_t)(n0 + 1));

    #pragma unroll 1
    for (int t = 0; t < T; ++t) {
        // --- next step's RNG first: 288 independent ALU ops the scheduler
        //     interleaves into the float chains below ---
        const uint4 kn = g_stepkeys[t + 1];
        const uint32_t nba_n = tf_bits32(kn.x, kn.y, (uint32_t)n0);
        const uint32_t nbb_n = tf_bits32(kn.x, kn.y, (uint32_t)(n0 + 1));
        const uint32_t uba_n = tf_bits32(kn.z, kn.w, (uint32_t)n0);
        const uint32_t ubb_n = tf_bits32(kn.z, kn.w, (uint32_t)(n0 + 1));

        const float2 Iv = *(const float2*)ip;

        // --- step t float update (consumes bits computed last iteration) ---
        float spa, va, spb, vb;
        lif_update(Va, Ta, aa, sa, nmv.x, Iv.x, nba, uba, spa, va);
        lif_update(Vb, Tb, ab, sb, nmv.y, Iv.y, nbb, ubb, spb, vb);

        *(float2*)sp = make_float2(spa, spb);
        *(float2*)vp = make_float2(va, vb);

        ip += BN; sp += BN; vp += BN;
        nba = nba_n; nbb = nbb_n; uba = uba_n; ubb = ubb_n;
    }
}

// ---------------------------------------------------------------------------
// Launch. Graph-capturable: kernel launches only.
// ---------------------------------------------------------------------------
extern "C" void kernel_launch(void* const* d_in, const int* in_sizes, int n_in,
                              void* d_out, int out_size) {
    const float* input = (const float*)d_in[0];
    const float* V0    = (const float*)d_in[1];
    const float* Vth0  = (const float*)d_in[2];
    const float* ad0   = (const float*)d_in[3];
    const float* sy0   = (const float*)d_in[4];
    const float* nm0   = (const float*)d_in[5];

    const int BN = in_sizes[1];              // B*N
    const int T  = in_sizes[0] / BN;         // time steps

    lif_init_keys<<<(T + 127) / 128, 128>>>(T);

    const int threads = 32;                  // 1-warp blocks: 4096 blocks
    const int nthreads_total = BN / 2;
    const int blocks = (nthreads_total + threads - 1) / threads;
    lif_main<<<blocks, threads>>>(input, V0, Vth0, ad0, sy0, nm0,
                                  (float*)d_out, T, BN);
}

// round 17
// speedup vs baseline: 1.0603x; 1.0026x over previous
#include <cuda_runtime.h>
#include <cstdint>

// Pin accurate log regardless of harness fast-math flags.
extern "C" __device__ float __nv_logf(float);

// ---------------------------------------------------------------------------
// JAX threefry2x32, exact: rotations {13,15,26,6,17,29,16,24}, 5+1 injections
// ---------------------------------------------------------------------------
#define TFRND(r) { x0 += x1; x1 = __funnelshift_l(x1, x1, (r)); x1 ^= x0; }

__device__ __forceinline__ uint2 threefry2x32(uint32_t k0, uint32_t k1,
                                              uint32_t x0, uint32_t x1) {
    uint32_t k2 = k0 ^ k1 ^ 0x1BD11BDAu;
    x0 += k0; x1 += k1;
    TFRND(13) TFRND(15) TFRND(26) TFRND(6)
    x0 += k1; x1 += k2 + 1u;
    TFRND(17) TFRND(29) TFRND(16) TFRND(24)
    x0 += k2; x1 += k0 + 2u;
    TFRND(13) TFRND(15) TFRND(26) TFRND(6)
    x0 += k0; x1 += k1 + 3u;
    TFRND(17) TFRND(29) TFRND(16) TFRND(24)
    x0 += k1; x1 += k2 + 4u;
    TFRND(13) TFRND(15) TFRND(26) TFRND(6)
    x0 += k2; x1 += k0 + 5u;
    return make_uint2(x0, x1);
}

// 32-bit random bits, partitionable mode: one block per element, xor halves.
__device__ __forceinline__ uint32_t tf_bits32(uint32_t k0, uint32_t k1, uint32_t idx) {
    uint2 r = threefry2x32(k0, k1, 0u, idx);
    return r.x ^ r.y;
}

// ---------------------------------------------------------------------------
// XLA ErfInv f32 (Giles poly) with XLA Log1p: u=a+1; d=u-1;
// log1p = (d==0) ? a : log(u)*a/d.  Branchy form (rare arms) = fewest instrs.
// ---------------------------------------------------------------------------
__device__ __forceinline__ float erfinv_xla(float x) {
    float a = __fmul_rn(-x, x);
    float u = __fadd_rn(a, 1.0f);
    float d = __fadd_rn(u, -1.0f);
    float l;
    if (d == 0.0f) {
        l = a;
    } else {
        l = __fdiv_rn(__fmul_rn(__nv_logf(u), a), d);
    }
    float w = -l;
    float p;
    if (w < 5.0f) {
        w = __fadd_rn(w, -2.5f);
        p = 2.81022636e-08f;
        p = fmaf(p, w, 3.43273939e-07f);
        p = fmaf(p, w, -3.5233877e-06f);
        p = fmaf(p, w, -4.39150654e-06f);
        p = fmaf(p, w, 0.00021858087f);
        p = fmaf(p, w, -0.00125372503f);
        p = fmaf(p, w, -0.00417768164f);
        p = fmaf(p, w, 0.246640727f);
        p = fmaf(p, w, 1.50140941f);
    } else {
        w = __fadd_rn(__fsqrt_rn(w), -3.0f);
        p = -0.000200214257f;
        p = fmaf(p, w, 0.000100950558f);
        p = fmaf(p, w, 0.00134934322f);
        p = fmaf(p, w, -0.00367342844f);
        p = fmaf(p, w, 0.00573950773f);
        p = fmaf(p, w, -0.0076224613f);
        p = fmaf(p, w, 0.00943887047f);
        p = fmaf(p, w, 1.00167406f);
        p = fmaf(p, w, 2.83297682f);
    }
    return __fmul_rn(p, x);
}

// ---------------------------------------------------------------------------
// XLA fast-tanh f32 (Eigen rational poly), logistic = 0.5 + 0.5*tanh(x/2)
// ---------------------------------------------------------------------------
__device__ __forceinline__ float tanh_xla(float x) {
    const float kClamp = 7.90531110763549805f;
    float cx = fminf(fmaxf(x, -kClamp), kClamp);
    float x2 = __fmul_rn(cx, cx);
    float np_;
    np_ = fmaf(x2, -2.76076847742355e-16f, 2.00018790482477e-13f);
    np_ = fmaf(x2, np_, -8.60467152213735e-11f);
    np_ = fmaf(x2, np_, 5.12229709037114e-08f);
    np_ = fmaf(x2, np_, 1.48572235717979e-05f);
    np_ = fmaf(x2, np_, 6.37261928875436e-04f);
    np_ = fmaf(x2, np_, 4.89352455891786e-03f);
    float num = __fmul_rn(cx, np_);
    float dq;
    dq = fmaf(x2, 1.19825839466702e-06f, 1.18534705686654e-04f);
    dq = fmaf(x2, dq, 2.26843463243900e-03f);
    dq = fmaf(x2, dq, 4.89352518554385e-03f);
    float r = __fdiv_rn(num, dq);
    return (fabsf(x) < 0.0004f) ? x : r;
}

__device__ __forceinline__ float sigmoid_xla(float x) {
    return fmaf(0.5f, tanh_xla(__fmul_rn(0.5f, x)), 0.5f);
}

// ---------------------------------------------------------------------------
// Per-step (noise_key, spike_key), partitionable semantics:
//   key_t = tf((0,42),(0,t));  k_noise = tf(key_t,(0,0));  k_spike = tf(key_t,(0,1))
// 512 entries, zero-initialized: reading index T (last-iter prefetch) is
// deterministic and its results are never consumed.
// ---------------------------------------------------------------------------
__device__ uint4 g_stepkeys[512];

__global__ void lif_init_keys(int T) {
    int t = blockIdx.x * blockDim.x + threadIdx.x;
    if (t >= T) return;
    uint2 kt = threefry2x32(0u, 42u, 0u, (uint32_t)t);
    uint2 kn = threefry2x32(kt.x, kt.y, 0u, 0u);
    uint2 ks = threefry2x32(kt.x, kt.y, 0u, 1u);
    g_stepkeys[t] = make_uint4(kn.x, kn.y, ks.x, ks.y);
}

// ---------------------------------------------------------------------------
// One neuron-step, bit-identical float sequence to the XLA lowering.
// (The uniform(LO,1) max(LO,.) is omitted: fn>=0 and monotone rounding make
//  fma(fn,2,LO) >= LO on every input, so the max was an identity.)
// ---------------------------------------------------------------------------
__device__ __forceinline__ void lif_update(
    float& V, float& Th, float& ad, float& sy, float nm,
    float Iin, uint32_t nb, uint32_t ub,
    float& sf_out, float& v_out)
{
    const float LO = -0.99999994039535522461f;     // nextafterf(-1, 0)
    const float SQRT2 = 1.41421353816986083984f;   // f32(np.sqrt(2))

    // noise = 0.1 * (sqrt2 * erfinv(uniform(LO, 1)))
    float fn = __fadd_rn(__uint_as_float((nb >> 9) | 0x3f800000u), -1.0f);
    float un = __fadd_rn(__fmul_rn(fn, 2.0f), LO);   // >= LO always; max removed
    float nrm = __fmul_rn(SQRT2, erfinv_xla(un));
    float noise = __fmul_rn(nrm, 0.1f);

    // I_eff = I*syn + neuromod - adapt   (unfused)
    float Ieff = __fadd_rn(__fadd_rn(__fmul_rn(Iin, sy), nm), -ad);
    // V = V + (I_eff - V)*0.05 + noise   (unfused)
    float dV = __fmul_rn(__fadd_rn(Ieff, -V), 0.05f);
    V = __fadd_rn(__fadd_rn(V, dV), noise);

    // spike: uniform(0,1) < sigmoid(V - Vth)
    float p  = sigmoid_xla(__fadd_rn(V, -Th));
    float uu = __fadd_rn(__uint_as_float((ub >> 9) | 0x3f800000u), -1.0f);
    bool spk = uu < p;

    V = spk ? 0.0f : V;

    float Th_ns = __fadd_rn(Th, -__fmul_rn(0.1f, __fadd_rn(Th, -1.0f)));
    Th = spk ? __fadd_rn(Th, 0.1f) : Th_ns;
    Th = fminf(fmaxf(Th, 0.5f), 2.0f);

    float sf = spk ? 1.0f : 0.0f;
    ad = __fadd_rn(__fmul_rn(ad, 0.9f), __fmul_rn(0.5f, sf));
    float t1 = __fadd_rn(1.0f, -__fmul_rn(0.1f, sf));
    float t2 = __fmul_rn(0.05f, __fadd_rn(1.0f, -sy));
    sy = __fadd_rn(__fmul_rn(sy, t1), t2);

    sf_out = sf;
    v_out = V;
}

// ---------------------------------------------------------------------------
// Main kernel (committed-best R16 structure): 2 adjacent neurons per thread;
// step t+1's threefry (288 straight-line ALU ops) computed before step t's
// branchy float phase; running pointers; float2 I/O; select-free key
// prefetch. New: keys staged in SHARED memory (one-time block copy), so the
// per-iteration key fetch at the head of the filler is a 29-cyc LDS instead
// of a 39-cyc LDG.  Block = 32: 4096 blocks, ~27/SM.
// ---------------------------------------------------------------------------
__global__ void __launch_bounds__(32, 28)
lif_main(const float* __restrict__ I,
         const float* __restrict__ V0,  const float* __restrict__ Vth0,
         const float* __restrict__ ad0, const float* __restrict__ sy0,
         const float* __restrict__ nm0,
         float* __restrict__ out, int T, int BN)
{
    __shared__ uint4 s_keys[208];            // T up to 207; T+1 read is valid

    const int tid = blockIdx.x * blockDim.x + threadIdx.x;
    const int n0 = tid * 2;
    if (n0 >= BN) return;

    // One-time copy of the step keys into shared memory (T+1 entries so the
    // unconditional [t+1] prefetch stays in-bounds; entry T is zeroed).
    for (int i = threadIdx.x; i <= T; i += 32)
        s_keys[i] = g_stepkeys[i];
    __syncthreads();

    float2 Vv  = ((const float2*)V0)[tid];
    float2 Thv = ((const float2*)Vth0)[tid];
    float2 adv = ((const float2*)ad0)[tid];
    float2 syv = ((const float2*)sy0)[tid];
    const float2 nmv = ((const float2*)nm0)[tid];

    float Va = Vv.x,  Vb = Vv.y;
    float Ta = Thv.x, Tb = Thv.y;
    float aa = adv.x, ab = adv.y;
    float sa = syv.x, sb = syv.y;

    // Running pointers: advance by BN floats per step (no per-iter IMAD).
    const float* __restrict__ ip = I + (size_t)n0;
    float* __restrict__ sp = out + (size_t)n0;
    float* __restrict__ vp = out + (size_t)T * (size_t)BN + (size_t)n0;

    // Prologue: bits for step 0.
    uint4 k = s_keys[0];
    uint32_t nba = tf_bits32(k.x, k.y, (uint32_t)n0);
    uint32_t nbb = tf_bits32(k.x, k.y, (uint32_t)(n0 + 1));
    uint32_t uba = tf_bits32(k.z, k.w, (uint32_t)n0);
    uint32_t ubb = tf_bits32(k.z, k.w, (uint32_t)(n0 + 1));

    #pragma unroll 1
    for (int t = 0; t < T; ++t) {
        // --- next step's RNG first: 288 independent ALU ops the scheduler
        //     interleaves into the float chains below ---
        const uint4 kn = s_keys[t + 1];
        const uint32_t nba_n = tf_bits32(kn.x, kn.y, (uint32_t)n0);
        const uint32_t nbb_n = tf_bits32(kn.x, kn.y, (uint32_t)(n0 + 1));
        const uint32_t uba_n = tf_bits32(kn.z, kn.w, (uint32_t)n0);
        const uint32_t ubb_n = tf_bits32(kn.z, kn.w, (uint32_t)(n0 + 1));

        const float2 Iv = *(const float2*)ip;

        // --- step t float update (consumes bits computed last iteration) ---
        float spa, va, spb, vb;
        lif_update(Va, Ta, aa, sa, nmv.x, Iv.x, nba, uba, spa, va);
        lif_update(Vb, Tb, ab, sb, nmv.y, Iv.y, nbb, ubb, spb, vb);

        *(float2*)sp = make_float2(spa, spb);
        *(float2*)vp = make_float2(va, vb);

        ip += BN; sp += BN; vp += BN;
        nba = nba_n; nbb = nbb_n; uba = uba_n; ubb = ubb_n;
    }
}

// ---------------------------------------------------------------------------
// Launch. Graph-capturable: kernel launches only.
// ---------------------------------------------------------------------------
extern "C" void kernel_launch(void* const* d_in, const int* in_sizes, int n_in,
                              void* d_out, int out_size) {
    const float* input = (const float*)d_in[0];
    const float* V0    = (const float*)d_in[1];
    const float* Vth0  = (const float*)d_in[2];
    const float* ad0   = (const float*)d_in[3];
    const float* sy0   = (const float*)d_in[4];
    const float* nm0   = (const float*)d_in[5];

    const int BN = in_sizes[1];              // B*N
    const int T  = in_sizes[0] / BN;         // time steps

    lif_init_keys<<<(T + 127) / 128, 128>>>(T);

    const int threads = 32;                  // 1-warp blocks: 4096 blocks
    const int nthreads_total = BN / 2;
    const int blocks = (nthreads_total + threads - 1) / threads;
    lif_main<<<blocks, threads>>>(input, V0, Vth0, ad0, sy0, nm0,
                                  (float*)d_out, T, BN);
}